// round 14
// baseline (speedup 1.0000x reference)
#include <cuda_runtime.h>
#include <cuda_fp16.h>
#include <math.h>
#include <stdint.h>

#define CB 2
#define CT 2048
#define CD 1024
#define CH 16
#define CHD 64

// ---------------------------------------------------------------------------
// Device scratch (no cudaMalloc allowed)
// ---------------------------------------------------------------------------
__device__ __align__(128) __half g_qkvh[(size_t)CB * CT * 3 * CD];  // qkv fp16 (Q cols pre-scaled)
__device__ __align__(128) __half g_xh[(size_t)CB * CT * CD];        // x fp16
__device__ __align__(128) __half g_yh[(size_t)CB * CT * CD];        // y fp16
__device__ __align__(128) __half g_w1t[(size_t)3 * CD * CD];        // W1^T [N,K]
__device__ __align__(128) __half g_w2t[(size_t)CD * CD];            // W2^T [N,K]

// Q pre-scale: 1/sqrt(64) * log2(e)
#define QSCALE 0.1803368801111244f

// ---------------------------------------------------------------------------
// Low-level helpers
// ---------------------------------------------------------------------------
__device__ __forceinline__ uint32_t smem_u32(const void* p) {
    uint32_t a;
    asm("{ .reg .u64 t; cvta.to.shared.u64 t, %1; cvt.u32.u64 %0, t; }" : "=r"(a) : "l"(p));
    return a;
}
__device__ __forceinline__ void cpasync16(uint32_t s, const void* g) {
    asm volatile("cp.async.cg.shared.global [%0], [%1], 16;" :: "r"(s), "l"(g));
}
__device__ __forceinline__ void cp_commit() {
    asm volatile("cp.async.commit_group;" ::: "memory");
}
template <int N>
__device__ __forceinline__ void cp_wait() {
    asm volatile("cp.async.wait_group %0;" :: "n"(N) : "memory");
}
__device__ __forceinline__ void ldsm4(uint32_t* r, uint32_t addr) {
    asm volatile("ldmatrix.sync.aligned.m8n8.x4.shared.b16 {%0,%1,%2,%3}, [%4];"
                 : "=r"(r[0]), "=r"(r[1]), "=r"(r[2]), "=r"(r[3]) : "r"(addr));
}
__device__ __forceinline__ void ldsm4t(uint32_t* r, uint32_t addr) {
    asm volatile("ldmatrix.sync.aligned.m8n8.x4.trans.shared.b16 {%0,%1,%2,%3}, [%4];"
                 : "=r"(r[0]), "=r"(r[1]), "=r"(r[2]), "=r"(r[3]) : "r"(addr));
}
__device__ __forceinline__ void mma16816(float* d, const uint32_t* a, const uint32_t* b) {
    asm volatile(
        "mma.sync.aligned.m16n8k16.row.col.f32.f16.f16.f32 "
        "{%0,%1,%2,%3}, {%4,%5,%6,%7}, {%8,%9}, {%0,%1,%2,%3};"
        : "+f"(d[0]), "+f"(d[1]), "+f"(d[2]), "+f"(d[3])
        : "r"(a[0]), "r"(a[1]), "r"(a[2]), "r"(a[3]), "r"(b[0]), "r"(b[1]));
}
__device__ __forceinline__ uint32_t swz128(uint32_t b) { return b ^ ((b >> 3) & 0x70); }
__device__ __forceinline__ uint32_t pack_f16(float a, float b) {
    __half2 v = __floats2half2_rn(a, b);
    return *(uint32_t*)&v;
}
__device__ __forceinline__ float fexp2(float x) {
    float y;
    asm("ex2.approx.ftz.f32 %0, %1;" : "=f"(y) : "f"(x));
    return y;
}

// ---------------------------------------------------------------------------
// Merged prep: x fp32->fp16 convert + W1/W2 transpose-convert, one launch.
// ---------------------------------------------------------------------------
#define NB_X  4096
#define NB_W1 3072
#define NB_W2 1024

__global__ __launch_bounds__(256) void prep_kernel(
    const float* __restrict__ x, __half* __restrict__ xh,
    const float* __restrict__ W1, __half* __restrict__ w1t,
    const float* __restrict__ W2, __half* __restrict__ w2t)
{
    int bid = blockIdx.x;
    int tid = threadIdx.x;
    if (bid < NB_X) {
        int i = bid * 256 + tid;
        float4 v = ((const float4*)x)[i];
        ((uint2*)xh)[i] = make_uint2(pack_f16(v.x, v.y), pack_f16(v.z, v.w));
        return;
    }
    __shared__ float t[32][33];
    const float* W;
    __half* outp;
    int N, bx, by;
    if (bid < NB_X + NB_W1) {
        int r = bid - NB_X;
        W = W1; outp = w1t; N = 3 * CD;
        bx = r % 96; by = r / 96;
    } else {
        int r = bid - NB_X - NB_W1;
        W = W2; outp = w2t; N = CD;
        bx = r % 32; by = r / 32;
    }
    int n0 = bx * 32, k0 = by * 32;
    int tx = tid & 31, ty = tid >> 5;
#pragma unroll
    for (int j = 0; j < 4; j++)
        t[ty + j * 8][tx] = W[(size_t)(k0 + ty + j * 8) * N + n0 + tx];
    __syncthreads();
#pragma unroll
    for (int j = 0; j < 4; j++)
        outp[(size_t)(n0 + ty + j * 8) * CD + k0 + tx] = __float2half_rn(t[tx][ty + j * 8]);
}

// ---------------------------------------------------------------------------
// HMMA fp16 GEMM: CTA 256x128, 512 threads, BK=128 super-chunks, 2 stages,
// one barrier per super-chunk. NEW: explicit 1-deep B-fragment prefetch —
// every ldsm b has 8 MMAs of latency cover.
// ---------------------------------------------------------------------------
#define SUPA 32768
#define SUPB 16384
#define SUP_STAGE (2 * SUPA + 2 * SUPB)   // 98304
#define GSMEM (2 * SUP_STAGE)             // 196608

template <bool F16OUT>
__global__ __launch_bounds__(512, 1) void gemm_f16_kernel(
    const __half* __restrict__ Ag, const __half* __restrict__ Bg,
    const float* __restrict__ bias, float* __restrict__ Cf,
    __half* __restrict__ Ch, int qcols, int N, int K)
{
    extern __shared__ char smem[];
    const uint32_t sbase = smem_u32(smem);
    const int tid = threadIdx.x;
    const int wid = tid >> 5;
    const int lid = tid & 31;
    const int wm = wid & 7;
    const int wn = wid >> 3;
    const int bm = blockIdx.y * 256;
    const int bn = blockIdx.x * 128;

    const int nsup = K >> 7;

    auto load_super = [&](int buf, int k0) {
        uint32_t sb = sbase + buf * SUP_STAGE;
#pragma unroll
        for (int i = 0; i < 12; i++) {
            int c = tid + (i << 9);
            if (c < 4096) {
                int sub = c >> 11;
                int cc = c & 2047;
                int row = cc >> 3, seg = cc & 7;
                uint32_t dst = sb + sub * SUPA + swz128((row << 7) + (seg << 4));
                cpasync16(dst, Ag + (size_t)(bm + row) * K + k0 + sub * 64 + (seg << 3));
            } else {
                int cc = c - 4096;
                int sub = cc >> 10;
                int c2 = cc & 1023;
                int row = c2 >> 3, seg = c2 & 7;
                uint32_t dst = sb + 2 * SUPA + sub * SUPB + swz128((row << 7) + (seg << 4));
                cpasync16(dst, Bg + (size_t)(bn + row) * K + k0 + sub * 64 + (seg << 3));
            }
        }
        cp_commit();
    };

    // B fragment address for (ks, pi) within a 64-k subtile
    auto boffset = [&](int ks, int pi) -> uint32_t {
        return swz128(((wn * 64 + pi * 16 + (lid & 7) + ((lid >> 4) << 3)) << 7) +
                      ((ks * 2 + ((lid >> 3) & 1)) << 4));
    };

    float d[2][8][4];
#pragma unroll
    for (int mi = 0; mi < 2; mi++)
#pragma unroll
        for (int ni = 0; ni < 8; ni++)
#pragma unroll
            for (int r = 0; r < 4; r++) d[mi][ni][r] = 0.0f;

    load_super(0, 0);

    for (int c = 0; c < nsup; c++) {
        cp_wait<0>();
        __syncthreads();
        if (c + 1 < nsup) load_super((c + 1) & 1, (c + 1) << 7);

        const uint32_t sb = sbase + (c & 1) * SUP_STAGE;
#pragma unroll
        for (int sub = 0; sub < 2; sub++) {
            const uint32_t aT = sb + sub * SUPA;
            const uint32_t bT = sb + 2 * SUPA + sub * SUPB;

            uint32_t bf[2][4];
            ldsm4(bf[0], bT + boffset(0, 0));    // preload first B fragment

#pragma unroll
            for (int ks = 0; ks < 4; ks++) {
                uint32_t a4[2][4];
#pragma unroll
                for (int mi = 0; mi < 2; mi++) {
                    uint32_t off = swz128(((wm * 32 + mi * 16 + (lid & 15)) << 7) +
                                          ((ks * 2 + (lid >> 4)) << 4));
                    ldsm4(a4[mi], aT + off);
                }
#pragma unroll
                for (int pi = 0; pi < 4; pi++) {
                    const int idx = ks * 4 + pi;
                    const int cur = idx & 1;
                    if (idx + 1 < 16) {
                        const int nk = (idx + 1) >> 2, np = (idx + 1) & 3;
                        ldsm4(bf[cur ^ 1], bT + boffset(nk, np));
                    }
#pragma unroll
                    for (int mi = 0; mi < 2; mi++)
#pragma unroll
                        for (int sub2 = 0; sub2 < 2; sub2++)
                            mma16816(d[mi][pi * 2 + sub2], a4[mi], bf[cur] + sub2 * 2);
                }
            }
        }
    }

#pragma unroll
    for (int mi = 0; mi < 2; mi++) {
        int row = bm + wm * 32 + mi * 16 + (lid >> 2);
#pragma unroll
        for (int ni = 0; ni < 8; ni++) {
            int col = bn + wn * 64 + ni * 8 + ((lid & 3) << 1);
            float2 bv = *(const float2*)&bias[col];
            float v00 = d[mi][ni][0] + bv.x, v01 = d[mi][ni][1] + bv.y;
            float v10 = d[mi][ni][2] + bv.x, v11 = d[mi][ni][3] + bv.y;
            if (F16OUT) {
                float qs = (col < qcols) ? QSCALE : 1.0f;
                v00 *= qs; v01 *= qs; v10 *= qs; v11 *= qs;
                *(uint32_t*)&Ch[(size_t)row * N + col] = pack_f16(v00, v01);
                *(uint32_t*)&Ch[(size_t)(row + 8) * N + col] = pack_f16(v10, v11);
            } else {
                *(float2*)&Cf[(size_t)row * N + col] = make_float2(v00, v01);
                *(float2*)&Cf[(size_t)(row + 8) * N + col] = make_float2(v10, v11);
            }
        }
    }
}

// ---------------------------------------------------------------------------
// HMMA fp16 flash attention, 128-key chunks; base-2 softmax (Q pre-scaled).
// 2-stage KV ring, single barrier per chunk.
// NEW: diagonal chunk skips fully-masked column-blocks (pi > w) in S and
// fully-zero key-blocks (kp > w) in PV.
// ---------------------------------------------------------------------------
#define AQT 16384
#define AKT2 16384
#define AKV_STAGE2 (2 * AKT2)
#define ASMEM (AQT + 2 * AKV_STAGE2)       // 81920; 2 CTAs/SM

__global__ __launch_bounds__(256, 2) void attn_f16_kernel(
    const __half* __restrict__ qkvh, __half* __restrict__ yh)
{
    extern __shared__ char smem[];
    const uint32_t sbase = smem_u32(smem);
    const int tid = threadIdx.x;
    const int w = tid >> 5;
    const int lid = tid & 31;
    const int qt = gridDim.x - 1 - blockIdx.x;
    const int h  = blockIdx.y;
    const int b  = blockIdx.z;
    const int qbase = qt * 128;
    const int nch = qt + 1;

    const uint32_t sQ = sbase;
    const uint32_t sKV = sbase + AQT;

    const size_t rowbase = (size_t)b * CT * 3 * CD + (size_t)h * CHD;

#pragma unroll
    for (int i = 0; i < 4; i++) {
        int c = tid + (i << 8);
        int row = c >> 3;
        int seg = c & 7;
        uint32_t so = swz128((row << 7) + (seg << 4));
        cpasync16(sQ + so, qkvh + rowbase + (size_t)(qbase + row) * (3 * CD) + (seg << 3));
    }

    auto load_kv = [&](int buf, int kt0) {
        uint32_t sb = sKV + buf * AKV_STAGE2;
#pragma unroll
        for (int i = 0; i < 8; i++) {
            int c = tid + (i << 8);
            int tile = c >> 10;
            int row = (c >> 3) & 127;
            int seg = c & 7;
            uint32_t so = swz128((row << 7) + (seg << 4));
            size_t ga = rowbase + (size_t)(kt0 + row) * (3 * CD) + (seg << 3) +
                        (tile ? 2 * CD : CD);
            cpasync16(sb + tile * AKT2 + so, qkvh + ga);
        }
        cp_commit();
    };

    load_kv(0, 0);

    float m0 = -INFINITY, m1 = -INFINITY, l0 = 0.0f, l1 = 0.0f;
    float oacc[8][4];
#pragma unroll
    for (int nb = 0; nb < 8; nb++)
#pragma unroll
        for (int r = 0; r < 4; r++) oacc[nb][r] = 0.0f;

    for (int c = 0; c < nch; c++) {
        cp_wait<0>();
        __syncthreads();
        if (c + 1 < nch) load_kv((c + 1) & 1, (c + 1) << 7);

        const uint32_t sb = sKV + (c & 1) * AKV_STAGE2;
        const uint32_t sK = sb, sV = sb + AKT2;
        const bool diag = (c == qt);

        uint32_t qf[4][4];
#pragma unroll
        for (int ks = 0; ks < 4; ks++) {
            uint32_t off = swz128(((w * 16 + (lid & 15)) << 7) +
                                  ((ks * 2 + (lid >> 4)) << 4));
            ldsm4(qf[ks], sQ + off);
        }

        // ---- S = Q' @ K^T over 128 keys (skip pi > w on diagonal) ----
        float sacc[16][4];
#pragma unroll
        for (int nb = 0; nb < 16; nb++)
#pragma unroll
            for (int r = 0; r < 4; r++) sacc[nb][r] = 0.0f;

#pragma unroll
        for (int ks = 0; ks < 4; ks++) {
#pragma unroll
            for (int pi = 0; pi < 8; pi++) {
                if (diag && pi > w) continue;    // fully-masked column block
                uint32_t boff = swz128(((pi * 16 + (lid & 7) + ((lid >> 4) << 3)) << 7) +
                                       ((ks * 2 + ((lid >> 3) & 1)) << 4));
                uint32_t k4[4];
                ldsm4(k4, sK + boff);
#pragma unroll
                for (int sub = 0; sub < 2; sub++)
                    mma16816(sacc[pi * 2 + sub], qf[ks], k4 + sub * 2);
            }
        }

        // ---- causal mask (all 16 blocks; uncomputed ones also set -inf) ----
        const int rin0 = w * 16 + (lid >> 2);
        const int rin1 = rin0 + 8;
        if (diag) {
#pragma unroll
            for (int nb = 0; nb < 16; nb++) {
                int col = nb * 8 + ((lid & 3) << 1);
                if (col > rin0)     sacc[nb][0] = -INFINITY;
                if (col + 1 > rin0) sacc[nb][1] = -INFINITY;
                if (col > rin1)     sacc[nb][2] = -INFINITY;
                if (col + 1 > rin1) sacc[nb][3] = -INFINITY;
            }
        }

        // ---- online softmax (base-2) ----
        {
            float mx0 = -INFINITY, mx1 = -INFINITY;
#pragma unroll
            for (int nb = 0; nb < 16; nb++) {
                mx0 = fmaxf(mx0, fmaxf(sacc[nb][0], sacc[nb][1]));
                mx1 = fmaxf(mx1, fmaxf(sacc[nb][2], sacc[nb][3]));
            }
            mx0 = fmaxf(mx0, __shfl_xor_sync(0xffffffffu, mx0, 1));
            mx0 = fmaxf(mx0, __shfl_xor_sync(0xffffffffu, mx0, 2));
            mx1 = fmaxf(mx1, __shfl_xor_sync(0xffffffffu, mx1, 1));
            mx1 = fmaxf(mx1, __shfl_xor_sync(0xffffffffu, mx1, 2));
            float mn0 = fmaxf(m0, mx0), mn1 = fmaxf(m1, mx1);
            float f0 = fexp2(m0 - mn0), f1 = fexp2(m1 - mn1);
            float s0 = 0.0f, s1 = 0.0f;
#pragma unroll
            for (int nb = 0; nb < 16; nb++) {
                sacc[nb][0] = fexp2(sacc[nb][0] - mn0);
                sacc[nb][1] = fexp2(sacc[nb][1] - mn0);
                sacc[nb][2] = fexp2(sacc[nb][2] - mn1);
                sacc[nb][3] = fexp2(sacc[nb][3] - mn1);
                s0 += sacc[nb][0] + sacc[nb][1];
                s1 += sacc[nb][2] + sacc[nb][3];
            }
            s0 += __shfl_xor_sync(0xffffffffu, s0, 1);
            s0 += __shfl_xor_sync(0xffffffffu, s0, 2);
            s1 += __shfl_xor_sync(0xffffffffu, s1, 1);
            s1 += __shfl_xor_sync(0xffffffffu, s1, 2);
            l0 = l0 * f0 + s0; l1 = l1 * f1 + s1;
            m0 = mn0; m1 = mn1;
#pragma unroll
            for (int nb = 0; nb < 8; nb++) {
                oacc[nb][0] *= f0; oacc[nb][1] *= f0;
                oacc[nb][2] *= f1; oacc[nb][3] *= f1;
            }
        }

        // ---- O += P @ V over 128 keys (skip kp > w on diagonal: P == 0) ----
#pragma unroll
        for (int kp = 0; kp < 8; kp++) {
            if (diag && kp > w) continue;
            uint32_t ph[4];
            ph[0] = pack_f16(sacc[2 * kp][0], sacc[2 * kp][1]);
            ph[1] = pack_f16(sacc[2 * kp][2], sacc[2 * kp][3]);
            ph[2] = pack_f16(sacc[2 * kp + 1][0], sacc[2 * kp + 1][1]);
            ph[3] = pack_f16(sacc[2 * kp + 1][2], sacc[2 * kp + 1][3]);
            const int mi = lid >> 3, r8 = lid & 7;
#pragma unroll
            for (int pi = 0; pi < 4; pi++) {
                uint32_t voff = swz128(((kp * 16 + ((mi & 1) << 3) + r8) << 7) +
                                       ((pi * 16 + ((mi >> 1) << 3)) << 1));
                uint32_t v4[4];
                ldsm4t(v4, sV + voff);
#pragma unroll
                for (int sub = 0; sub < 2; sub++)
                    mma16816(oacc[pi * 2 + sub], ph, v4 + sub * 2);
            }
        }
    }

    // ---- epilogue ----
    const float inv0 = 1.0f / l0, inv1 = 1.0f / l1;
    const int row0 = qbase + w * 16 + (lid >> 2);
    __half* yhb = yh + (size_t)b * CT * CD + (size_t)h * CHD;
#pragma unroll
    for (int nb = 0; nb < 8; nb++) {
        int col = nb * 8 + ((lid & 3) << 1);
        *(uint32_t*)&yhb[(size_t)row0 * CD + col] =
            pack_f16(oacc[nb][0] * inv0, oacc[nb][1] * inv0);
        *(uint32_t*)&yhb[(size_t)(row0 + 8) * CD + col] =
            pack_f16(oacc[nb][2] * inv1, oacc[nb][3] * inv1);
    }
}

// ---------------------------------------------------------------------------
// Launch
// ---------------------------------------------------------------------------
extern "C" void kernel_launch(void* const* d_in, const int* in_sizes, int n_in,
                              void* d_out, int out_size)
{
    (void)in_sizes; (void)n_in; (void)out_size;
    const float* x  = (const float*)d_in[0];
    const float* W1 = (const float*)d_in[1];
    const float* b1 = (const float*)d_in[2];
    const float* W2 = (const float*)d_in[3];
    const float* b2 = (const float*)d_in[4];
    float* out = (float*)d_out;

    __half *qkvh, *xh, *yh, *w1t, *w2t;
    cudaGetSymbolAddress((void**)&qkvh, g_qkvh);
    cudaGetSymbolAddress((void**)&xh, g_xh);
    cudaGetSymbolAddress((void**)&yh, g_yh);
    cudaGetSymbolAddress((void**)&w1t, g_w1t);
    cudaGetSymbolAddress((void**)&w2t, g_w2t);

    cudaFuncSetAttribute(gemm_f16_kernel<true>,
                         cudaFuncAttributeMaxDynamicSharedMemorySize, GSMEM);
    cudaFuncSetAttribute(gemm_f16_kernel<false>,
                         cudaFuncAttributeMaxDynamicSharedMemorySize, GSMEM);
    cudaFuncSetAttribute(attn_f16_kernel,
                         cudaFuncAttributeMaxDynamicSharedMemorySize, ASMEM);

    const int M = CB * CT;                 // 4096

    prep_kernel<<<NB_X + NB_W1 + NB_W2, 256>>>(x, xh, W1, w1t, W2, w2t);

    gemm_f16_kernel<true><<<dim3(3 * CD / 128, M / 256), 512, GSMEM>>>(
        xh, w1t, b1, nullptr, qkvh, CD, 3 * CD, CD);

    attn_f16_kernel<<<dim3(CT / 128, CH, CB), 256, ASMEM>>>(qkvh, yh);

    gemm_f16_kernel<false><<<dim3(CD / 128, M / 256), 512, GSMEM>>>(
        yh, w2t, b2, out, nullptr, 0, CD, CD);
}

// round 15
// speedup vs baseline: 1.0673x; 1.0673x over previous
#include <cuda_runtime.h>
#include <cuda_fp16.h>
#include <math.h>
#include <stdint.h>

#define CB 2
#define CT 2048
#define CD 1024
#define CH 16
#define CHD 64

// ---------------------------------------------------------------------------
// Device scratch (no cudaMalloc allowed)
// ---------------------------------------------------------------------------
__device__ __align__(128) __half g_qkvh[(size_t)CB * CT * 3 * CD];  // qkv fp16 (Q cols pre-scaled)
__device__ __align__(128) __half g_xh[(size_t)CB * CT * CD];        // x fp16
__device__ __align__(128) __half g_yh[(size_t)CB * CT * CD];        // y fp16
__device__ __align__(128) __half g_w1t[(size_t)3 * CD * CD];        // W1^T [N,K]
__device__ __align__(128) __half g_w2t[(size_t)CD * CD];            // W2^T [N,K]

// Q pre-scale: 1/sqrt(64) * log2(e)
#define QSCALE 0.1803368801111244f

// ---------------------------------------------------------------------------
// Low-level helpers
// ---------------------------------------------------------------------------
__device__ __forceinline__ uint32_t smem_u32(const void* p) {
    uint32_t a;
    asm("{ .reg .u64 t; cvta.to.shared.u64 t, %1; cvt.u32.u64 %0, t; }" : "=r"(a) : "l"(p));
    return a;
}
__device__ __forceinline__ void cpasync16(uint32_t s, const void* g) {
    asm volatile("cp.async.cg.shared.global [%0], [%1], 16;" :: "r"(s), "l"(g));
}
__device__ __forceinline__ void cp_commit() {
    asm volatile("cp.async.commit_group;" ::: "memory");
}
template <int N>
__device__ __forceinline__ void cp_wait() {
    asm volatile("cp.async.wait_group %0;" :: "n"(N) : "memory");
}
__device__ __forceinline__ void ldsm4(uint32_t* r, uint32_t addr) {
    asm volatile("ldmatrix.sync.aligned.m8n8.x4.shared.b16 {%0,%1,%2,%3}, [%4];"
                 : "=r"(r[0]), "=r"(r[1]), "=r"(r[2]), "=r"(r[3]) : "r"(addr));
}
__device__ __forceinline__ void ldsm4t(uint32_t* r, uint32_t addr) {
    asm volatile("ldmatrix.sync.aligned.m8n8.x4.trans.shared.b16 {%0,%1,%2,%3}, [%4];"
                 : "=r"(r[0]), "=r"(r[1]), "=r"(r[2]), "=r"(r[3]) : "r"(addr));
}
__device__ __forceinline__ void mma16816(float* d, const uint32_t* a, const uint32_t* b) {
    asm volatile(
        "mma.sync.aligned.m16n8k16.row.col.f32.f16.f16.f32 "
        "{%0,%1,%2,%3}, {%4,%5,%6,%7}, {%8,%9}, {%0,%1,%2,%3};"
        : "+f"(d[0]), "+f"(d[1]), "+f"(d[2]), "+f"(d[3])
        : "r"(a[0]), "r"(a[1]), "r"(a[2]), "r"(a[3]), "r"(b[0]), "r"(b[1]));
}
__device__ __forceinline__ uint32_t swz128(uint32_t b) { return b ^ ((b >> 3) & 0x70); }
__device__ __forceinline__ uint32_t pack_f16(float a, float b) {
    __half2 v = __floats2half2_rn(a, b);
    return *(uint32_t*)&v;
}
__device__ __forceinline__ float fexp2(float x) {
    float y;
    asm("ex2.approx.ftz.f32 %0, %1;" : "=f"(y) : "f"(x));
    return y;
}

// ---------------------------------------------------------------------------
// Merged prep: x fp32->fp16 convert + W1/W2 transpose-convert, one launch.
// Block ranges: [0, NB_X) convert; [NB_X, NB_X+NB_W1) W1^T; rest W2^T.
// ---------------------------------------------------------------------------
#define NB_X  4096                       // (4096*1024/4)/256
#define NB_W1 3072                       // (3072/32)*(1024/32)
#define NB_W2 1024                       // (1024/32)*(1024/32)

__global__ __launch_bounds__(256) void prep_kernel(
    const float* __restrict__ x, __half* __restrict__ xh,
    const float* __restrict__ W1, __half* __restrict__ w1t,
    const float* __restrict__ W2, __half* __restrict__ w2t)
{
    int bid = blockIdx.x;
    int tid = threadIdx.x;
    if (bid < NB_X) {
        int i = bid * 256 + tid;
        float4 v = ((const float4*)x)[i];
        ((uint2*)xh)[i] = make_uint2(pack_f16(v.x, v.y), pack_f16(v.z, v.w));
        return;
    }
    // transpose path: 32x32 tile, tx=tid&31, ty=tid>>5 (8 rows/pass)
    __shared__ float t[32][33];
    const float* W;
    __half* outp;
    int N, bx, by;
    if (bid < NB_X + NB_W1) {
        int r = bid - NB_X;
        W = W1; outp = w1t; N = 3 * CD;
        bx = r % 96; by = r / 96;
    } else {
        int r = bid - NB_X - NB_W1;
        W = W2; outp = w2t; N = CD;
        bx = r % 32; by = r / 32;
    }
    int n0 = bx * 32, k0 = by * 32;
    int tx = tid & 31, ty = tid >> 5;
#pragma unroll
    for (int j = 0; j < 4; j++)
        t[ty + j * 8][tx] = W[(size_t)(k0 + ty + j * 8) * N + n0 + tx];
    __syncthreads();
#pragma unroll
    for (int j = 0; j < 4; j++)
        outp[(size_t)(n0 + ty + j * 8) * CD + k0 + tx] = __float2half_rn(t[tx][ty + j * 8]);
}

// ---------------------------------------------------------------------------
// HMMA fp16 GEMM: CTA 256x128, 512 threads, BK=128 super-chunks,
// 2 super-stages, one barrier per super-chunk.
// ---------------------------------------------------------------------------
#define SUPA 32768
#define SUPB 16384
#define SUP_STAGE (2 * SUPA + 2 * SUPB)   // 98304
#define GSMEM (2 * SUP_STAGE)             // 196608

template <bool F16OUT>
__global__ __launch_bounds__(512, 1) void gemm_f16_kernel(
    const __half* __restrict__ Ag, const __half* __restrict__ Bg,
    const float* __restrict__ bias, float* __restrict__ Cf,
    __half* __restrict__ Ch, int qcols, int N, int K)
{
    extern __shared__ char smem[];
    const uint32_t sbase = smem_u32(smem);
    const int tid = threadIdx.x;
    const int wid = tid >> 5;
    const int lid = tid & 31;
    const int wm = wid & 7;
    const int wn = wid >> 3;
    const int bm = blockIdx.y * 256;
    const int bn = blockIdx.x * 128;

    const int nsup = K >> 7;

    auto load_super = [&](int buf, int k0) {
        uint32_t sb = sbase + buf * SUP_STAGE;
#pragma unroll
        for (int i = 0; i < 12; i++) {
            int c = tid + (i << 9);
            if (c < 4096) {
                int sub = c >> 11;
                int cc = c & 2047;
                int row = cc >> 3, seg = cc & 7;
                uint32_t dst = sb + sub * SUPA + swz128((row << 7) + (seg << 4));
                cpasync16(dst, Ag + (size_t)(bm + row) * K + k0 + sub * 64 + (seg << 3));
            } else {
                int cc = c - 4096;
                int sub = cc >> 10;
                int c2 = cc & 1023;
                int row = c2 >> 3, seg = c2 & 7;
                uint32_t dst = sb + 2 * SUPA + sub * SUPB + swz128((row << 7) + (seg << 4));
                cpasync16(dst, Bg + (size_t)(bn + row) * K + k0 + sub * 64 + (seg << 3));
            }
        }
        cp_commit();
    };

    float d[2][8][4];
#pragma unroll
    for (int mi = 0; mi < 2; mi++)
#pragma unroll
        for (int ni = 0; ni < 8; ni++)
#pragma unroll
            for (int r = 0; r < 4; r++) d[mi][ni][r] = 0.0f;

    load_super(0, 0);

    for (int c = 0; c < nsup; c++) {
        cp_wait<0>();
        __syncthreads();
        if (c + 1 < nsup) load_super((c + 1) & 1, (c + 1) << 7);

        const uint32_t sb = sbase + (c & 1) * SUP_STAGE;
#pragma unroll
        for (int sub = 0; sub < 2; sub++) {
            const uint32_t aT = sb + sub * SUPA;
            const uint32_t bT = sb + 2 * SUPA + sub * SUPB;
#pragma unroll
            for (int ks = 0; ks < 4; ks++) {
                uint32_t a4[2][4];
#pragma unroll
                for (int mi = 0; mi < 2; mi++) {
                    uint32_t off = swz128(((wm * 32 + mi * 16 + (lid & 15)) << 7) +
                                          ((ks * 2 + (lid >> 4)) << 4));
                    ldsm4(a4[mi], aT + off);
                }
#pragma unroll
                for (int pi = 0; pi < 4; pi++) {
                    uint32_t boff = swz128(((wn * 64 + pi * 16 + (lid & 7) + ((lid >> 4) << 3)) << 7) +
                                           ((ks * 2 + ((lid >> 3) & 1)) << 4));
                    uint32_t b4[4];
                    ldsm4(b4, bT + boff);
#pragma unroll
                    for (int mi = 0; mi < 2; mi++)
#pragma unroll
                        for (int sub2 = 0; sub2 < 2; sub2++)
                            mma16816(d[mi][pi * 2 + sub2], a4[mi], b4 + sub2 * 2);
                }
            }
        }
    }

#pragma unroll
    for (int mi = 0; mi < 2; mi++) {
        int row = bm + wm * 32 + mi * 16 + (lid >> 2);
#pragma unroll
        for (int ni = 0; ni < 8; ni++) {
            int col = bn + wn * 64 + ni * 8 + ((lid & 3) << 1);
            float2 bv = *(const float2*)&bias[col];
            float v00 = d[mi][ni][0] + bv.x, v01 = d[mi][ni][1] + bv.y;
            float v10 = d[mi][ni][2] + bv.x, v11 = d[mi][ni][3] + bv.y;
            if (F16OUT) {
                float qs = (col < qcols) ? QSCALE : 1.0f;
                v00 *= qs; v01 *= qs; v10 *= qs; v11 *= qs;
                *(uint32_t*)&Ch[(size_t)row * N + col] = pack_f16(v00, v01);
                *(uint32_t*)&Ch[(size_t)(row + 8) * N + col] = pack_f16(v10, v11);
            } else {
                *(float2*)&Cf[(size_t)row * N + col] = make_float2(v00, v01);
                *(float2*)&Cf[(size_t)(row + 8) * N + col] = make_float2(v10, v11);
            }
        }
    }
}

// ---------------------------------------------------------------------------
// HMMA fp16 flash attention, 128-key chunks: one softmax + one barrier per
// 128 keys. Q pre-scaled -> base-2 softmax. 2-stage KV ring, single barrier
// per chunk. Big causal tiles scheduled first.
// ---------------------------------------------------------------------------
#define AQT 16384
#define AKT2 16384                         // K tile: 128 keys x 128B
#define AKV_STAGE2 (2 * AKT2)              // K + V = 32KB
#define ASMEM (AQT + 2 * AKV_STAGE2)       // 81920; 2 CTAs/SM -> 160KB

__global__ __launch_bounds__(256, 2) void attn_f16_kernel(
    const __half* __restrict__ qkvh, __half* __restrict__ yh)
{
    extern __shared__ char smem[];
    const uint32_t sbase = smem_u32(smem);
    const int tid = threadIdx.x;
    const int w = tid >> 5;
    const int lid = tid & 31;
    const int qt = gridDim.x - 1 - blockIdx.x;   // big causal tiles first
    const int h  = blockIdx.y;
    const int b  = blockIdx.z;
    const int qbase = qt * 128;
    const int nch = qt + 1;                      // 128-key chunks

    const uint32_t sQ = sbase;
    const uint32_t sKV = sbase + AQT;

    const size_t rowbase = (size_t)b * CT * 3 * CD + (size_t)h * CHD;

    // Q load (joins KV group 0's commit)
#pragma unroll
    for (int i = 0; i < 4; i++) {
        int c = tid + (i << 8);
        int row = c >> 3;
        int seg = c & 7;
        uint32_t so = swz128((row << 7) + (seg << 4));
        cpasync16(sQ + so, qkvh + rowbase + (size_t)(qbase + row) * (3 * CD) + (seg << 3));
    }

    auto load_kv = [&](int buf, int kt0) {
        uint32_t sb = sKV + buf * AKV_STAGE2;
#pragma unroll
        for (int i = 0; i < 8; i++) {
            int c = tid + (i << 8);            // 0..2047 16B chunks
            int tile = c >> 10;                // 0 K, 1 V (128 rows each)
            int row = (c >> 3) & 127;
            int seg = c & 7;
            uint32_t so = swz128((row << 7) + (seg << 4));
            size_t ga = rowbase + (size_t)(kt0 + row) * (3 * CD) + (seg << 3) +
                        (tile ? 2 * CD : CD);
            cpasync16(sb + tile * AKT2 + so, qkvh + ga);
        }
        cp_commit();
    };

    load_kv(0, 0);

    float m0 = -INFINITY, m1 = -INFINITY, l0 = 0.0f, l1 = 0.0f;
    float oacc[8][4];
#pragma unroll
    for (int nb = 0; nb < 8; nb++)
#pragma unroll
        for (int r = 0; r < 4; r++) oacc[nb][r] = 0.0f;

    for (int c = 0; c < nch; c++) {
        cp_wait<0>();                    // drain stage c (only group outstanding)
        __syncthreads();                 // publish stage c; other slot fully read
        if (c + 1 < nch) load_kv((c + 1) & 1, (c + 1) << 7);

        const uint32_t sb = sKV + (c & 1) * AKV_STAGE2;
        const uint32_t sK = sb, sV = sb + AKT2;

        // Q fragments (reloaded per chunk to bound register pressure)
        uint32_t qf[4][4];
#pragma unroll
        for (int ks = 0; ks < 4; ks++) {
            uint32_t off = swz128(((w * 16 + (lid & 15)) << 7) +
                                  ((ks * 2 + (lid >> 4)) << 4));
            ldsm4(qf[ks], sQ + off);
        }

        // ---- S = Q' @ K^T over 128 keys ----
        float sacc[16][4];
#pragma unroll
        for (int nb = 0; nb < 16; nb++)
#pragma unroll
            for (int r = 0; r < 4; r++) sacc[nb][r] = 0.0f;

#pragma unroll
        for (int ks = 0; ks < 4; ks++) {
#pragma unroll
            for (int pi = 0; pi < 8; pi++) {
                uint32_t boff = swz128(((pi * 16 + (lid & 7) + ((lid >> 4) << 3)) << 7) +
                                       ((ks * 2 + ((lid >> 3) & 1)) << 4));
                uint32_t k4[4];
                ldsm4(k4, sK + boff);
#pragma unroll
                for (int sub = 0; sub < 2; sub++)
                    mma16816(sacc[pi * 2 + sub], qf[ks], k4 + sub * 2);
            }
        }

        // ---- causal mask (only the diagonal chunk c == qt) ----
        const int rin0 = w * 16 + (lid >> 2);   // row within tile
        const int rin1 = rin0 + 8;
        if (c == qt) {
#pragma unroll
            for (int nb = 0; nb < 16; nb++) {
                int col = nb * 8 + ((lid & 3) << 1);
                if (col > rin0)     sacc[nb][0] = -INFINITY;
                if (col + 1 > rin0) sacc[nb][1] = -INFINITY;
                if (col > rin1)     sacc[nb][2] = -INFINITY;
                if (col + 1 > rin1) sacc[nb][3] = -INFINITY;
            }
        }

        // ---- online softmax (base-2) over 128 cols ----
        {
            float mx0 = -INFINITY, mx1 = -INFINITY;
#pragma unroll
            for (int nb = 0; nb < 16; nb++) {
                mx0 = fmaxf(mx0, fmaxf(sacc[nb][0], sacc[nb][1]));
                mx1 = fmaxf(mx1, fmaxf(sacc[nb][2], sacc[nb][3]));
            }
            mx0 = fmaxf(mx0, __shfl_xor_sync(0xffffffffu, mx0, 1));
            mx0 = fmaxf(mx0, __shfl_xor_sync(0xffffffffu, mx0, 2));
            mx1 = fmaxf(mx1, __shfl_xor_sync(0xffffffffu, mx1, 1));
            mx1 = fmaxf(mx1, __shfl_xor_sync(0xffffffffu, mx1, 2));
            float mn0 = fmaxf(m0, mx0), mn1 = fmaxf(m1, mx1);
            float f0 = fexp2(m0 - mn0), f1 = fexp2(m1 - mn1);
            float s0 = 0.0f, s1 = 0.0f;
#pragma unroll
            for (int nb = 0; nb < 16; nb++) {
                sacc[nb][0] = fexp2(sacc[nb][0] - mn0);
                sacc[nb][1] = fexp2(sacc[nb][1] - mn0);
                sacc[nb][2] = fexp2(sacc[nb][2] - mn1);
                sacc[nb][3] = fexp2(sacc[nb][3] - mn1);
                s0 += sacc[nb][0] + sacc[nb][1];
                s1 += sacc[nb][2] + sacc[nb][3];
            }
            s0 += __shfl_xor_sync(0xffffffffu, s0, 1);
            s0 += __shfl_xor_sync(0xffffffffu, s0, 2);
            s1 += __shfl_xor_sync(0xffffffffu, s1, 1);
            s1 += __shfl_xor_sync(0xffffffffu, s1, 2);
            l0 = l0 * f0 + s0; l1 = l1 * f1 + s1;
            m0 = mn0; m1 = mn1;
#pragma unroll
            for (int nb = 0; nb < 8; nb++) {
                oacc[nb][0] *= f0; oacc[nb][1] *= f0;
                oacc[nb][2] *= f1; oacc[nb][3] *= f1;
            }
        }

        // ---- O += P @ V over 128 keys ----
#pragma unroll
        for (int kp = 0; kp < 8; kp++) {
            uint32_t ph[4];
            ph[0] = pack_f16(sacc[2 * kp][0], sacc[2 * kp][1]);
            ph[1] = pack_f16(sacc[2 * kp][2], sacc[2 * kp][3]);
            ph[2] = pack_f16(sacc[2 * kp + 1][0], sacc[2 * kp + 1][1]);
            ph[3] = pack_f16(sacc[2 * kp + 1][2], sacc[2 * kp + 1][3]);
            const int mi = lid >> 3, r8 = lid & 7;
#pragma unroll
            for (int pi = 0; pi < 4; pi++) {
                uint32_t voff = swz128(((kp * 16 + ((mi & 1) << 3) + r8) << 7) +
                                       ((pi * 16 + ((mi >> 1) << 3)) << 1));
                uint32_t v4[4];
                ldsm4t(v4, sV + voff);
#pragma unroll
                for (int sub = 0; sub < 2; sub++)
                    mma16816(oacc[pi * 2 + sub], ph, v4 + sub * 2);
            }
        }
    }

    // ---- epilogue: normalize, fp16 store ----
    const float inv0 = 1.0f / l0, inv1 = 1.0f / l1;
    const int row0 = qbase + w * 16 + (lid >> 2);
    __half* yhb = yh + (size_t)b * CT * CD + (size_t)h * CHD;
#pragma unroll
    for (int nb = 0; nb < 8; nb++) {
        int col = nb * 8 + ((lid & 3) << 1);
        *(uint32_t*)&yhb[(size_t)row0 * CD + col] =
            pack_f16(oacc[nb][0] * inv0, oacc[nb][1] * inv0);
        *(uint32_t*)&yhb[(size_t)(row0 + 8) * CD + col] =
            pack_f16(oacc[nb][2] * inv1, oacc[nb][3] * inv1);
    }
}

// ---------------------------------------------------------------------------
// Launch
// ---------------------------------------------------------------------------
extern "C" void kernel_launch(void* const* d_in, const int* in_sizes, int n_in,
                              void* d_out, int out_size)
{
    (void)in_sizes; (void)n_in; (void)out_size;
    const float* x  = (const float*)d_in[0];
    const float* W1 = (const float*)d_in[1];
    const float* b1 = (const float*)d_in[2];
    const float* W2 = (const float*)d_in[3];
    const float* b2 = (const float*)d_in[4];
    float* out = (float*)d_out;

    __half *qkvh, *xh, *yh, *w1t, *w2t;
    cudaGetSymbolAddress((void**)&qkvh, g_qkvh);
    cudaGetSymbolAddress((void**)&xh, g_xh);
    cudaGetSymbolAddress((void**)&yh, g_yh);
    cudaGetSymbolAddress((void**)&w1t, g_w1t);
    cudaGetSymbolAddress((void**)&w2t, g_w2t);

    cudaFuncSetAttribute(gemm_f16_kernel<true>,
                         cudaFuncAttributeMaxDynamicSharedMemorySize, GSMEM);
    cudaFuncSetAttribute(gemm_f16_kernel<false>,
                         cudaFuncAttributeMaxDynamicSharedMemorySize, GSMEM);
    cudaFuncSetAttribute(attn_f16_kernel,
                         cudaFuncAttributeMaxDynamicSharedMemorySize, ASMEM);

    const int M = CB * CT;                 // 4096

    // merged prep: x convert + W1^T + W2^T
    prep_kernel<<<NB_X + NB_W1 + NB_W2, 256>>>(x, xh, W1, w1t, W2, w2t);

    // qkv (fp16) = x @ W1 + b1 ; Q columns pre-scaled by QSCALE
    gemm_f16_kernel<true><<<dim3(3 * CD / 128, M / 256), 512, GSMEM>>>(
        xh, w1t, b1, nullptr, qkvh, CD, 3 * CD, CD);

    // flash attention -> y (fp16), 128-key chunks
    attn_f16_kernel<<<dim3(CT / 128, CH, CB), 256, ASMEM>>>(qkvh, yh);

    // out (fp32) = y @ W2 + b2
    gemm_f16_kernel<false><<<dim3(CD / 128, M / 256), 512, GSMEM>>>(
        yh, w2t, b2, out, nullptr, 0, CD, CD);
}

// round 16
// speedup vs baseline: 1.0987x; 1.0294x over previous
#include <cuda_runtime.h>
#include <cuda_fp16.h>
#include <math.h>
#include <stdint.h>

#define CB 2
#define CT 2048
#define CD 1024
#define CH 16
#define CHD 64

// ---------------------------------------------------------------------------
// Device scratch (no cudaMalloc allowed)
// ---------------------------------------------------------------------------
__device__ __align__(128) __half g_qkvh[(size_t)CB * CT * 3 * CD];  // qkv fp16 (Q cols pre-scaled)
__device__ __align__(128) __half g_xh[(size_t)CB * CT * CD];        // x fp16
__device__ __align__(128) __half g_yh[(size_t)CB * CT * CD];        // y fp16
__device__ __align__(128) __half g_w1t[(size_t)3 * CD * CD];        // W1^T [N,K]
__device__ __align__(128) __half g_w2t[(size_t)CD * CD];            // W2^T [N,K]

// Q pre-scale: 1/sqrt(64) * log2(e)
#define QSCALE 0.1803368801111244f

// ---------------------------------------------------------------------------
// Low-level helpers
// ---------------------------------------------------------------------------
__device__ __forceinline__ uint32_t smem_u32(const void* p) {
    uint32_t a;
    asm("{ .reg .u64 t; cvta.to.shared.u64 t, %1; cvt.u32.u64 %0, t; }" : "=r"(a) : "l"(p));
    return a;
}
__device__ __forceinline__ void cpasync16(uint32_t s, const void* g) {
    asm volatile("cp.async.cg.shared.global [%0], [%1], 16;" :: "r"(s), "l"(g));
}
__device__ __forceinline__ void cp_commit() {
    asm volatile("cp.async.commit_group;" ::: "memory");
}
template <int N>
__device__ __forceinline__ void cp_wait() {
    asm volatile("cp.async.wait_group %0;" :: "n"(N) : "memory");
}
__device__ __forceinline__ void ldsm4(uint32_t* r, uint32_t addr) {
    asm volatile("ldmatrix.sync.aligned.m8n8.x4.shared.b16 {%0,%1,%2,%3}, [%4];"
                 : "=r"(r[0]), "=r"(r[1]), "=r"(r[2]), "=r"(r[3]) : "r"(addr));
}
__device__ __forceinline__ void ldsm4t(uint32_t* r, uint32_t addr) {
    asm volatile("ldmatrix.sync.aligned.m8n8.x4.trans.shared.b16 {%0,%1,%2,%3}, [%4];"
                 : "=r"(r[0]), "=r"(r[1]), "=r"(r[2]), "=r"(r[3]) : "r"(addr));
}
__device__ __forceinline__ void mma16816(float* d, const uint32_t* a, const uint32_t* b) {
    asm volatile(
        "mma.sync.aligned.m16n8k16.row.col.f32.f16.f16.f32 "
        "{%0,%1,%2,%3}, {%4,%5,%6,%7}, {%8,%9}, {%0,%1,%2,%3};"
        : "+f"(d[0]), "+f"(d[1]), "+f"(d[2]), "+f"(d[3])
        : "r"(a[0]), "r"(a[1]), "r"(a[2]), "r"(a[3]), "r"(b[0]), "r"(b[1]));
}
__device__ __forceinline__ uint32_t swz128(uint32_t b) { return b ^ ((b >> 3) & 0x70); }
__device__ __forceinline__ uint32_t pack_f16(float a, float b) {
    __half2 v = __floats2half2_rn(a, b);
    return *(uint32_t*)&v;
}
__device__ __forceinline__ float fexp2(float x) {
    float y;
    asm("ex2.approx.ftz.f32 %0, %1;" : "=f"(y) : "f"(x));
    return y;
}
// packed fp16x2 exp2: two exponentials per MUFU instruction
__device__ __forceinline__ uint32_t exp2_h2(float a, float b) {
    uint32_t h = pack_f16(a, b);
    uint32_t r;
    asm("ex2.approx.f16x2 %0, %1;" : "=r"(r) : "r"(h));
    return r;
}

// ---------------------------------------------------------------------------
// Merged prep: x fp32->fp16 convert + W1/W2 transpose-convert, one launch.
// ---------------------------------------------------------------------------
#define NB_X  4096
#define NB_W1 3072
#define NB_W2 1024

__global__ __launch_bounds__(256) void prep_kernel(
    const float* __restrict__ x, __half* __restrict__ xh,
    const float* __restrict__ W1, __half* __restrict__ w1t,
    const float* __restrict__ W2, __half* __restrict__ w2t)
{
    int bid = blockIdx.x;
    int tid = threadIdx.x;
    if (bid < NB_X) {
        int i = bid * 256 + tid;
        float4 v = ((const float4*)x)[i];
        ((uint2*)xh)[i] = make_uint2(pack_f16(v.x, v.y), pack_f16(v.z, v.w));
        return;
    }
    __shared__ float t[32][33];
    const float* W;
    __half* outp;
    int N, bx, by;
    if (bid < NB_X + NB_W1) {
        int r = bid - NB_X;
        W = W1; outp = w1t; N = 3 * CD;
        bx = r % 96; by = r / 96;
    } else {
        int r = bid - NB_X - NB_W1;
        W = W2; outp = w2t; N = CD;
        bx = r % 32; by = r / 32;
    }
    int n0 = bx * 32, k0 = by * 32;
    int tx = tid & 31, ty = tid >> 5;
#pragma unroll
    for (int j = 0; j < 4; j++)
        t[ty + j * 8][tx] = W[(size_t)(k0 + ty + j * 8) * N + n0 + tx];
    __syncthreads();
#pragma unroll
    for (int j = 0; j < 4; j++)
        outp[(size_t)(n0 + ty + j * 8) * CD + k0 + tx] = __float2half_rn(t[tx][ty + j * 8]);
}

// ---------------------------------------------------------------------------
// HMMA fp16 GEMM (unchanged from R13/R15): CTA 256x128, 512 threads,
// BK=128 super-chunks, 2 super-stages, one barrier per super-chunk.
// ---------------------------------------------------------------------------
#define SUPA 32768
#define SUPB 16384
#define SUP_STAGE (2 * SUPA + 2 * SUPB)   // 98304
#define GSMEM (2 * SUP_STAGE)             // 196608

template <bool F16OUT>
__global__ __launch_bounds__(512, 1) void gemm_f16_kernel(
    const __half* __restrict__ Ag, const __half* __restrict__ Bg,
    const float* __restrict__ bias, float* __restrict__ Cf,
    __half* __restrict__ Ch, int qcols, int N, int K)
{
    extern __shared__ char smem[];
    const uint32_t sbase = smem_u32(smem);
    const int tid = threadIdx.x;
    const int wid = tid >> 5;
    const int lid = tid & 31;
    const int wm = wid & 7;
    const int wn = wid >> 3;
    const int bm = blockIdx.y * 256;
    const int bn = blockIdx.x * 128;

    const int nsup = K >> 7;

    auto load_super = [&](int buf, int k0) {
        uint32_t sb = sbase + buf * SUP_STAGE;
#pragma unroll
        for (int i = 0; i < 12; i++) {
            int c = tid + (i << 9);
            if (c < 4096) {
                int sub = c >> 11;
                int cc = c & 2047;
                int row = cc >> 3, seg = cc & 7;
                uint32_t dst = sb + sub * SUPA + swz128((row << 7) + (seg << 4));
                cpasync16(dst, Ag + (size_t)(bm + row) * K + k0 + sub * 64 + (seg << 3));
            } else {
                int cc = c - 4096;
                int sub = cc >> 10;
                int c2 = cc & 1023;
                int row = c2 >> 3, seg = c2 & 7;
                uint32_t dst = sb + 2 * SUPA + sub * SUPB + swz128((row << 7) + (seg << 4));
                cpasync16(dst, Bg + (size_t)(bn + row) * K + k0 + sub * 64 + (seg << 3));
            }
        }
        cp_commit();
    };

    float d[2][8][4];
#pragma unroll
    for (int mi = 0; mi < 2; mi++)
#pragma unroll
        for (int ni = 0; ni < 8; ni++)
#pragma unroll
            for (int r = 0; r < 4; r++) d[mi][ni][r] = 0.0f;

    load_super(0, 0);

    for (int c = 0; c < nsup; c++) {
        cp_wait<0>();
        __syncthreads();
        if (c + 1 < nsup) load_super((c + 1) & 1, (c + 1) << 7);

        const uint32_t sb = sbase + (c & 1) * SUP_STAGE;
#pragma unroll
        for (int sub = 0; sub < 2; sub++) {
            const uint32_t aT = sb + sub * SUPA;
            const uint32_t bT = sb + 2 * SUPA + sub * SUPB;
#pragma unroll
            for (int ks = 0; ks < 4; ks++) {
                uint32_t a4[2][4];
#pragma unroll
                for (int mi = 0; mi < 2; mi++) {
                    uint32_t off = swz128(((wm * 32 + mi * 16 + (lid & 15)) << 7) +
                                          ((ks * 2 + (lid >> 4)) << 4));
                    ldsm4(a4[mi], aT + off);
                }
#pragma unroll
                for (int pi = 0; pi < 4; pi++) {
                    uint32_t boff = swz128(((wn * 64 + pi * 16 + (lid & 7) + ((lid >> 4) << 3)) << 7) +
                                           ((ks * 2 + ((lid >> 3) & 1)) << 4));
                    uint32_t b4[4];
                    ldsm4(b4, bT + boff);
#pragma unroll
                    for (int mi = 0; mi < 2; mi++)
#pragma unroll
                        for (int sub2 = 0; sub2 < 2; sub2++)
                            mma16816(d[mi][pi * 2 + sub2], a4[mi], b4 + sub2 * 2);
                }
            }
        }
    }

#pragma unroll
    for (int mi = 0; mi < 2; mi++) {
        int row = bm + wm * 32 + mi * 16 + (lid >> 2);
#pragma unroll
        for (int ni = 0; ni < 8; ni++) {
            int col = bn + wn * 64 + ni * 8 + ((lid & 3) << 1);
            float2 bv = *(const float2*)&bias[col];
            float v00 = d[mi][ni][0] + bv.x, v01 = d[mi][ni][1] + bv.y;
            float v10 = d[mi][ni][2] + bv.x, v11 = d[mi][ni][3] + bv.y;
            if (F16OUT) {
                float qs = (col < qcols) ? QSCALE : 1.0f;
                v00 *= qs; v01 *= qs; v10 *= qs; v11 *= qs;
                *(uint32_t*)&Ch[(size_t)row * N + col] = pack_f16(v00, v01);
                *(uint32_t*)&Ch[(size_t)(row + 8) * N + col] = pack_f16(v10, v11);
            } else {
                *(float2*)&Cf[(size_t)row * N + col] = make_float2(v00, v01);
                *(float2*)&Cf[(size_t)(row + 8) * N + col] = make_float2(v10, v11);
            }
        }
    }
}

// ---------------------------------------------------------------------------
// HMMA fp16 flash attention, 128-key chunks.
// NEW vs R15: softmax fused into PV loop with ex2.approx.f16x2 (2 exp2 per
// MUFU instr, P produced directly as packed fp16), and the row-sum l
// computed by an extra ones-column MMA per kp (fp32 accum on tensor core;
// no FADD chain, no sum-shfls).
// ---------------------------------------------------------------------------
#define AQT 16384
#define AKT2 16384                         // K tile: 128 keys x 128B
#define AKV_STAGE2 (2 * AKT2)              // K + V = 32KB
#define ASMEM (AQT + 2 * AKV_STAGE2)       // 81920; 2 CTAs/SM -> 160KB

__global__ __launch_bounds__(256, 2) void attn_f16_kernel(
    const __half* __restrict__ qkvh, __half* __restrict__ yh)
{
    extern __shared__ char smem[];
    const uint32_t sbase = smem_u32(smem);
    const int tid = threadIdx.x;
    const int w = tid >> 5;
    const int lid = tid & 31;
    const int qt = gridDim.x - 1 - blockIdx.x;   // big causal tiles first
    const int h  = blockIdx.y;
    const int b  = blockIdx.z;
    const int qbase = qt * 128;
    const int nch = qt + 1;

    const uint32_t sQ = sbase;
    const uint32_t sKV = sbase + AQT;

    const size_t rowbase = (size_t)b * CT * 3 * CD + (size_t)h * CHD;

    // Q load (joins KV group 0's commit)
#pragma unroll
    for (int i = 0; i < 4; i++) {
        int c = tid + (i << 8);
        int row = c >> 3;
        int seg = c & 7;
        uint32_t so = swz128((row << 7) + (seg << 4));
        cpasync16(sQ + so, qkvh + rowbase + (size_t)(qbase + row) * (3 * CD) + (seg << 3));
    }

    auto load_kv = [&](int buf, int kt0) {
        uint32_t sb = sKV + buf * AKV_STAGE2;
#pragma unroll
        for (int i = 0; i < 8; i++) {
            int c = tid + (i << 8);
            int tile = c >> 10;
            int row = (c >> 3) & 127;
            int seg = c & 7;
            uint32_t so = swz128((row << 7) + (seg << 4));
            size_t ga = rowbase + (size_t)(kt0 + row) * (3 * CD) + (seg << 3) +
                        (tile ? 2 * CD : CD);
            cpasync16(sb + tile * AKT2 + so, qkvh + ga);
        }
        cp_commit();
    };

    load_kv(0, 0);

    float m0 = -INFINITY, m1 = -INFINITY, l0 = 0.0f, l1 = 0.0f;
    float oacc[8][4];
#pragma unroll
    for (int nb = 0; nb < 8; nb++)
#pragma unroll
        for (int r = 0; r < 4; r++) oacc[nb][r] = 0.0f;

    const uint32_t ones2 = 0x3C003C00u;          // fp16 {1.0, 1.0}
    uint32_t bOnes[2] = {ones2, ones2};

    for (int c = 0; c < nch; c++) {
        cp_wait<0>();
        __syncthreads();
        if (c + 1 < nch) load_kv((c + 1) & 1, (c + 1) << 7);

        const uint32_t sb = sKV + (c & 1) * AKV_STAGE2;
        const uint32_t sK = sb, sV = sb + AKT2;

        uint32_t qf[4][4];
#pragma unroll
        for (int ks = 0; ks < 4; ks++) {
            uint32_t off = swz128(((w * 16 + (lid & 15)) << 7) +
                                  ((ks * 2 + (lid >> 4)) << 4));
            ldsm4(qf[ks], sQ + off);
        }

        // ---- S = Q' @ K^T over 128 keys ----
        float sacc[16][4];
#pragma unroll
        for (int nb = 0; nb < 16; nb++)
#pragma unroll
            for (int r = 0; r < 4; r++) sacc[nb][r] = 0.0f;

#pragma unroll
        for (int ks = 0; ks < 4; ks++) {
#pragma unroll
            for (int pi = 0; pi < 8; pi++) {
                uint32_t boff = swz128(((pi * 16 + (lid & 7) + ((lid >> 4) << 3)) << 7) +
                                       ((ks * 2 + ((lid >> 3) & 1)) << 4));
                uint32_t k4[4];
                ldsm4(k4, sK + boff);
#pragma unroll
                for (int sub = 0; sub < 2; sub++)
                    mma16816(sacc[pi * 2 + sub], qf[ks], k4 + sub * 2);
            }
        }

        // ---- causal mask (only the diagonal chunk c == qt) ----
        const int rin0 = w * 16 + (lid >> 2);
        const int rin1 = rin0 + 8;
        if (c == qt) {
#pragma unroll
            for (int nb = 0; nb < 16; nb++) {
                int col = nb * 8 + ((lid & 3) << 1);
                if (col > rin0)     sacc[nb][0] = -INFINITY;
                if (col + 1 > rin0) sacc[nb][1] = -INFINITY;
                if (col > rin1)     sacc[nb][2] = -INFINITY;
                if (col + 1 > rin1) sacc[nb][3] = -INFINITY;
            }
        }

        // ---- running max + rescale (base-2) ----
        float mn0, mn1, f0, f1;
        {
            float mx0 = -INFINITY, mx1 = -INFINITY;
#pragma unroll
            for (int nb = 0; nb < 16; nb++) {
                mx0 = fmaxf(mx0, fmaxf(sacc[nb][0], sacc[nb][1]));
                mx1 = fmaxf(mx1, fmaxf(sacc[nb][2], sacc[nb][3]));
            }
            mx0 = fmaxf(mx0, __shfl_xor_sync(0xffffffffu, mx0, 1));
            mx0 = fmaxf(mx0, __shfl_xor_sync(0xffffffffu, mx0, 2));
            mx1 = fmaxf(mx1, __shfl_xor_sync(0xffffffffu, mx1, 1));
            mx1 = fmaxf(mx1, __shfl_xor_sync(0xffffffffu, mx1, 2));
            mn0 = fmaxf(m0, mx0); mn1 = fmaxf(m1, mx1);
            f0 = fexp2(m0 - mn0); f1 = fexp2(m1 - mn1);
            m0 = mn0; m1 = mn1;
#pragma unroll
            for (int nb = 0; nb < 8; nb++) {
                oacc[nb][0] *= f0; oacc[nb][1] *= f0;
                oacc[nb][2] *= f1; oacc[nb][3] *= f1;
            }
        }

        // ---- fused softmax + PV + l-MMA over 128 keys ----
        float lacc[4];
        lacc[0] = lacc[1] = lacc[2] = lacc[3] = 0.0f;
#pragma unroll
        for (int kp = 0; kp < 8; kp++) {
            uint32_t ph[4];
            ph[0] = exp2_h2(sacc[2 * kp][0] - mn0, sacc[2 * kp][1] - mn0);
            ph[1] = exp2_h2(sacc[2 * kp][2] - mn1, sacc[2 * kp][3] - mn1);
            ph[2] = exp2_h2(sacc[2 * kp + 1][0] - mn0, sacc[2 * kp + 1][1] - mn0);
            ph[3] = exp2_h2(sacc[2 * kp + 1][2] - mn1, sacc[2 * kp + 1][3] - mn1);
            mma16816(lacc, ph, bOnes);           // row sums on the tensor core
            const int mi = lid >> 3, r8 = lid & 7;
#pragma unroll
            for (int pi = 0; pi < 4; pi++) {
                uint32_t voff = swz128(((kp * 16 + ((mi & 1) << 3) + r8) << 7) +
                                       ((pi * 16 + ((mi >> 1) << 3)) << 1));
                uint32_t v4[4];
                ldsm4t(v4, sV + voff);
#pragma unroll
                for (int sub = 0; sub < 2; sub++)
                    mma16816(oacc[pi * 2 + sub], ph, v4 + sub * 2);
            }
        }
        l0 = l0 * f0 + lacc[0];
        l1 = l1 * f1 + lacc[2];
    }

    // ---- epilogue: normalize, fp16 store ----
    const float inv0 = 1.0f / l0, inv1 = 1.0f / l1;
    const int row0 = qbase + w * 16 + (lid >> 2);
    __half* yhb = yh + (size_t)b * CT * CD + (size_t)h * CHD;
#pragma unroll
    for (int nb = 0; nb < 8; nb++) {
        int col = nb * 8 + ((lid & 3) << 1);
        *(uint32_t*)&yhb[(size_t)row0 * CD + col] =
            pack_f16(oacc[nb][0] * inv0, oacc[nb][1] * inv0);
        *(uint32_t*)&yhb[(size_t)(row0 + 8) * CD + col] =
            pack_f16(oacc[nb][2] * inv1, oacc[nb][3] * inv1);
    }
}

// ---------------------------------------------------------------------------
// Launch
// ---------------------------------------------------------------------------
extern "C" void kernel_launch(void* const* d_in, const int* in_sizes, int n_in,
                              void* d_out, int out_size)
{
    (void)in_sizes; (void)n_in; (void)out_size;
    const float* x  = (const float*)d_in[0];
    const float* W1 = (const float*)d_in[1];
    const float* b1 = (const float*)d_in[2];
    const float* W2 = (const float*)d_in[3];
    const float* b2 = (const float*)d_in[4];
    float* out = (float*)d_out;

    __half *qkvh, *xh, *yh, *w1t, *w2t;
    cudaGetSymbolAddress((void**)&qkvh, g_qkvh);
    cudaGetSymbolAddress((void**)&xh, g_xh);
    cudaGetSymbolAddress((void**)&yh, g_yh);
    cudaGetSymbolAddress((void**)&w1t, g_w1t);
    cudaGetSymbolAddress((void**)&w2t, g_w2t);

    cudaFuncSetAttribute(gemm_f16_kernel<true>,
                         cudaFuncAttributeMaxDynamicSharedMemorySize, GSMEM);
    cudaFuncSetAttribute(gemm_f16_kernel<false>,
                         cudaFuncAttributeMaxDynamicSharedMemorySize, GSMEM);
    cudaFuncSetAttribute(attn_f16_kernel,
                         cudaFuncAttributeMaxDynamicSharedMemorySize, ASMEM);

    const int M = CB * CT;                 // 4096

    prep_kernel<<<NB_X + NB_W1 + NB_W2, 256>>>(x, xh, W1, w1t, W2, w2t);

    gemm_f16_kernel<true><<<dim3(3 * CD / 128, M / 256), 512, GSMEM>>>(
        xh, w1t, b1, nullptr, qkvh, CD, 3 * CD, CD);

    attn_f16_kernel<<<dim3(CT / 128, CH, CB), 256, ASMEM>>>(qkvh, yh);

    gemm_f16_kernel<false><<<dim3(CD / 128, M / 256), 512, GSMEM>>>(
        yh, w2t, b2, out, nullptr, 0, CD, CD);
}